// round 7
// baseline (speedup 1.0000x reference)
#include <cuda_runtime.h>
#include <cuda_bf16.h>
#include <math.h>
#include <stdint.h>

#define NNODES 50000
#define NPADM  50048
#define NMT    3128        // NPADM/16 mtiles
#define NEDGES 200000
#define TOTE   (NEDGES + NNODES)
#define EMB    300
#define EMB4   75
#define KPAD   320
#define NKT    20          // KPAD/16
#define NNT    40          // KPAD/8 ntiles
#define DK     256
#define BGR    1000
#define NPER   50
#define NLAYERS 5
#define PADF   16

// ---------------- scratch (device globals) ----------------
__device__ float g_h[NNODES * EMB];
__device__ float g_hW[NNODES * EMB];
// A fragments: [mtile][ktile][lane] -> uint4 (4 bf16x2 regs a0..a3)
__device__ uint4 g_hfa_hi[NMT * NKT * 32];
__device__ uint4 g_hfa_lo[NMT * NKT * 32];
// B fragments: [layer][ntile][ktile][lane] -> uint4 {b0_hi,b1_hi,b0_lo,b1_lo}
__device__ uint4 g_wfb[NLAYERS * NNT * NKT * 32];
__device__ float g_mf[BGR * EMB];
__device__ float g_ve_all[NLAYERS * 2 * EMB];
__device__ float g_Q[BGR * DK];
__device__ float g_qk[BGR * EMB];
__device__ float g_wsum[BGR * EMB];
__device__ float g_mean[BGR * EMB];
__device__ float g_wqt[EMB * DK];
__device__ float g_wvt[EMB * DK];
__device__ float g_mlt[EMB * DK];
__device__ float g_lgt[EMB * DK];
__device__ float g_ph1t[DK * 512];
// CSR
__device__ int g_deg[NNODES];
__device__ int g_off[NNODES + 1];
__device__ int g_cur[NNODES];
__device__ int g_csr_src[TOTE];
__device__ float2 g_csr_ea[TOTE];

// ---------------- helpers ----------------
__device__ __forceinline__ void split_pack(float v0, float v1, uint32_t& hi, uint32_t& lo)
{
    __nv_bfloat16 h0 = __float2bfloat16(v0);
    __nv_bfloat16 h1 = __float2bfloat16(v1);
    __nv_bfloat16 l0 = __float2bfloat16(v0 - __bfloat162float(h0));
    __nv_bfloat16 l1 = __float2bfloat16(v1 - __bfloat162float(h1));
    __nv_bfloat162 H = __halves2bfloat162(h0, h1);
    __nv_bfloat162 L = __halves2bfloat162(l0, l1);
    hi = *(uint32_t*)&H;
    lo = *(uint32_t*)&L;
}

#define MMA_BF16(d, a, b) asm volatile( \
    "mma.sync.aligned.m16n8k16.row.col.f32.bf16.bf16.f32 " \
    "{%0,%1,%2,%3},{%4,%5,%6,%7},{%8,%9},{%0,%1,%2,%3};\n" \
    : "+f"(d[0]), "+f"(d[1]), "+f"(d[2]), "+f"(d[3]) \
    : "r"((a)[0]), "r"((a)[1]), "r"((a)[2]), "r"((a)[3]), "r"((b)[0]), "r"((b)[1]))

// shared fragment-writer: block covers 16 node rows in hs[16][HSW], writes A frags
#define HSW 332
__device__ __forceinline__ void write_frags_from_smem(float (*hs)[HSW], int mtile,
                                                      int warp, int lane)
{
    int gid = lane >> 2, tig = lane & 3;
    for (int kt = warp; kt < NKT; kt += 4) {
        int kb = kt * 16;
        float v00 = hs[gid][kb + 2 * tig],     v01 = hs[gid][kb + 2 * tig + 1];
        float v10 = hs[gid + 8][kb + 2 * tig], v11 = hs[gid + 8][kb + 2 * tig + 1];
        float v20 = hs[gid][kb + 8 + 2 * tig],     v21 = hs[gid][kb + 8 + 2 * tig + 1];
        float v30 = hs[gid + 8][kb + 8 + 2 * tig], v31 = hs[gid + 8][kb + 8 + 2 * tig + 1];
        uint4 Hi, Lo;
        split_pack(v00, v01, Hi.x, Lo.x);
        split_pack(v10, v11, Hi.y, Lo.y);
        split_pack(v20, v21, Hi.z, Lo.z);
        split_pack(v30, v31, Hi.w, Lo.w);
        size_t idx = ((size_t)mtile * NKT + kt) * 32 + lane;
        g_hfa_hi[idx] = Hi;
        g_hfa_lo[idx] = Lo;
    }
}

// ---------------- node init -> A fragments ----------------
__global__ void __launch_bounds__(128) k_init_frag(const int* __restrict__ x_type,
                                                   const float* __restrict__ x_feat,
                                                   const float* __restrict__ x_emb,
                                                   const float* __restrict__ x_weight)
{
    __shared__ float hs[16][HSW];
    int tid = threadIdx.x, warp = tid >> 5, lane = tid & 31;
    int base = blockIdx.x * 16;
#pragma unroll
    for (int i = 0; i < 4; i++) {
        int row = warp * 4 + i;
        int n = base + row;
        int t = __ldg(x_type + n);
#pragma unroll
        for (int ch = 0; ch < 3; ch++) {
            int c = lane + 32 * ch;
            if (c < EMB4) {
                float4 acc = __ldg((const float4*)(x_emb + (size_t)t * EMB) + c);
#pragma unroll
                for (int k = 0; k < PADF; k++) {
                    float f = __ldg(x_feat + (size_t)n * PADF + k);
                    float4 w = __ldg((const float4*)(x_weight + (size_t)k * EMB) + c);
                    acc.x = fmaf(f, w.x, acc.x); acc.y = fmaf(f, w.y, acc.y);
                    acc.z = fmaf(f, w.z, acc.z); acc.w = fmaf(f, w.w, acc.w);
                }
                *(float4*)&hs[row][4 * c] = acc;
            }
        }
        hs[row][300 + lane] = 0.f;   // zero pad cols 300..331
    }
    __syncthreads();
    write_frags_from_smem(hs, blockIdx.x, warp, lane);
}

// ---------------- weight split -> B fragments (all layers, once) ----------------
__global__ void k_wsplit_frag(const float* __restrict__ mlp_w)
{
    int idx = blockIdx.x * blockDim.x + threadIdx.x;
    if (idx >= NLAYERS * NNT * NKT * 32) return;
    int lane = idx & 31;
    int kt = (idx >> 5) % NKT;
    int nt = (idx >> 5) / NKT % NNT;
    int l = idx / (32 * NKT * NNT);
    int gid = lane >> 2, tig = lane & 3;
    int j = nt * 8 + gid;
    int k0 = kt * 16 + 2 * tig;
    int k1 = k0 + 8;
    const float* W = mlp_w + (size_t)l * EMB * EMB + (size_t)j * EMB;
    float w00 = (j < EMB && k0 < EMB) ? __ldg(W + k0) : 0.f;
    float w01 = (j < EMB && k0 + 1 < EMB) ? __ldg(W + k0 + 1) : 0.f;
    float w10 = (j < EMB && k1 < EMB) ? __ldg(W + k1) : 0.f;
    float w11 = (j < EMB && k1 + 1 < EMB) ? __ldg(W + k1 + 1) : 0.f;
    uint4 o;
    split_pack(w00, w01, o.x, o.z);
    split_pack(w10, w11, o.y, o.w);
    g_wfb[idx] = o;
}

// ---------------- metal feature ----------------
__global__ void k_mf(const int* __restrict__ metal_type, const float* __restrict__ metal_feat,
                     const float* __restrict__ me1_w, const float* __restrict__ me1_b,
                     const float* __restrict__ me2)
{
    int idx = blockIdx.x * blockDim.x + threadIdx.x;
    if (idx >= BGR * EMB) return;
    int b = idx / EMB, j = idx % EMB;
    float acc = __ldg(me1_b + j) + __ldg(me2 + (size_t)__ldg(metal_type + b) * EMB + j);
#pragma unroll
    for (int k = 0; k < 17; k++)
        acc = fmaf(__ldg(metal_feat + (size_t)b * 17 + k), __ldg(me1_w + (size_t)j * 17 + k), acc);
    g_mf[idx] = acc;
}

// ---------------- transpose readout weights ----------------
__global__ void k_transpose_all(const float* __restrict__ wq, const float* __restrict__ wv,
                                const float* __restrict__ ml, const float* __restrict__ lg,
                                const float* __restrict__ ph1)
{
    int idx = blockIdx.x * blockDim.x + threadIdx.x;
    const int SZ1 = DK * EMB;
    if (idx < 4 * SZ1) {
        int w = idx / SZ1, i = idx % SZ1;
        int d = i / EMB, j = i % EMB;
        float v = (w == 0) ? wq[i] : (w == 1) ? wv[i] : (w == 2) ? ml[i] : lg[i];
        float* dst = (w == 0) ? g_wqt : (w == 1) ? g_wvt : (w == 2) ? g_mlt : g_lgt;
        dst[(size_t)j * DK + d] = v;
    } else {
        int i = idx - 4 * SZ1;
        if (i < 512 * DK) {
            int o = i / DK, d = i % DK;
            g_ph1t[(size_t)d * 512 + o] = ph1[i];
        }
    }
}

// ---------------- all layers' edge vectors ----------------
__global__ void k_ve_all(const float* __restrict__ ew1, const float* __restrict__ mlp_w)
{
    int o = (blockIdx.x * blockDim.x + threadIdx.x) >> 5;
    if (o >= NLAYERS * 2 * EMB) return;
    int lane = threadIdx.x & 31;
    int l = o / (2 * EMB);
    int rem = o % (2 * EMB);
    int w = rem / EMB, col = rem % EMB;
    const float* e = ew1 + (size_t)l * 2 * EMB + (size_t)w * EMB;
    const float* wr = mlp_w + (size_t)l * EMB * EMB + (size_t)col * EMB;
    float s = 0.f;
    for (int k = lane; k < EMB; k += 32) s = fmaf(__ldg(e + k), __ldg(wr + k), s);
#pragma unroll
    for (int off = 16; off; off >>= 1) s += __shfl_xor_sync(0xffffffffu, s, off);
    if (lane == 0) g_ve_all[o] = s;
}

// ---------------- CSR build ----------------
__global__ void k_deg_init() {
    int i = blockIdx.x * blockDim.x + threadIdx.x;
    if (i < NNODES) g_deg[i] = 1;
}
__global__ void k_deg_count(const int* __restrict__ eidx) {
    int e = blockIdx.x * blockDim.x + threadIdx.x;
    if (e < NEDGES) atomicAdd(&g_deg[__ldg(eidx + NEDGES + e)], 1);
}
__global__ void k_scan() {
    __shared__ int ps[1024];
    const int C = (NNODES + 1023) / 1024;
    int t = threadIdx.x;
    int base = t * C;
    int s = 0;
    for (int i = base; i < base + C && i < NNODES; i++) s += g_deg[i];
    ps[t] = s;
    __syncthreads();
    for (int off = 1; off < 1024; off <<= 1) {
        int v = (t >= off) ? ps[t - off] : 0;
        __syncthreads();
        ps[t] += v;
        __syncthreads();
    }
    int ex = (t == 0) ? 0 : ps[t - 1];
    for (int i = base; i < base + C && i < NNODES; i++) {
        g_off[i] = ex; g_cur[i] = ex;
        ex += g_deg[i];
    }
    if (t == 1023) g_off[NNODES] = TOTE;
}
__global__ void k_fill(const int* __restrict__ eidx, const float* __restrict__ eattr) {
    int idx = blockIdx.x * blockDim.x + threadIdx.x;
    if (idx >= TOTE) return;
    int src, col; float2 ea;
    if (idx < NEDGES) {
        src = __ldg(eidx + idx);
        col = __ldg(eidx + NEDGES + idx);
        ea = __ldg((const float2*)eattr + idx);
    } else {
        src = col = idx - NEDGES;
        ea = make_float2(0.f, 4.f);
    }
    int pos = atomicAdd(&g_cur[col], 1);
    g_csr_src[pos] = src;
    g_csr_ea[pos] = ea;
}

// ---------------- GEMM: hW = h @ W.T + b  (fragment-direct, no smem) ----------------
// CTA: 256 thr, warps 2(M)x4(N); tile 128(M) x 160(N); grid (391, 2).
__global__ void __launch_bounds__(256) k_gemm_frag(int layer, const float* __restrict__ bias)
{
    int tid = threadIdx.x, warp = tid >> 5, lane = tid & 31;
    int gid = lane >> 2, tig = lane & 3;
    int wm = warp & 1, wn = warp >> 1;
    int mt0 = blockIdx.x * 8 + wm * 4;
    int nt0 = blockIdx.y * 20 + wn * 5;

    float acc[4][5][4];
#pragma unroll
    for (int mt = 0; mt < 4; mt++)
#pragma unroll
        for (int nj = 0; nj < 5; nj++)
#pragma unroll
            for (int r = 0; r < 4; r++) acc[mt][nj][r] = 0.f;

    uint32_t a_hi[2][4][4], a_lo[2][4][4], bf[2][5][4];
    const uint4* Bf = g_wfb + (size_t)layer * NNT * NKT * 32;

#define LOADK(buf, kt_) do { \
    _Pragma("unroll") \
    for (int mt = 0; mt < 4; mt++) { \
        size_t ai = ((size_t)(mt0 + mt) * NKT + (kt_)) * 32 + lane; \
        *(uint4*)a_hi[buf][mt] = g_hfa_hi[ai]; \
        *(uint4*)a_lo[buf][mt] = g_hfa_lo[ai]; } \
    _Pragma("unroll") \
    for (int nj = 0; nj < 5; nj++) \
        if ((nt0 + nj) * 8 < EMB) \
            *(uint4*)bf[buf][nj] = Bf[((size_t)(nt0 + nj) * NKT + (kt_)) * 32 + lane]; \
} while (0)

    LOADK(0, 0);
    for (int kt = 0; kt < NKT; kt++) {
        int cur = kt & 1;
        if (kt < NKT - 1) LOADK(1 - cur, kt + 1);
        // pass 1: hi x hi
#pragma unroll
        for (int mt = 0; mt < 4; mt++)
#pragma unroll
            for (int nj = 0; nj < 5; nj++)
                if ((nt0 + nj) * 8 < EMB) MMA_BF16(acc[mt][nj], a_hi[cur][mt], bf[cur][nj]);
        // pass 2: lo x hi
#pragma unroll
        for (int mt = 0; mt < 4; mt++)
#pragma unroll
            for (int nj = 0; nj < 5; nj++)
                if ((nt0 + nj) * 8 < EMB) MMA_BF16(acc[mt][nj], a_lo[cur][mt], bf[cur][nj]);
        // pass 3: hi x lo
#pragma unroll
        for (int mt = 0; mt < 4; mt++)
#pragma unroll
            for (int nj = 0; nj < 5; nj++)
                if ((nt0 + nj) * 8 < EMB) MMA_BF16(acc[mt][nj], a_hi[cur][mt], bf[cur][nj] + 2);
    }
#undef LOADK

    // epilogue: + bias, store fp32
#pragma unroll
    for (int mt = 0; mt < 4; mt++) {
        int m = (mt0 + mt) * 16 + gid;
#pragma unroll
        for (int nj = 0; nj < 5; nj++) {
            int j = (nt0 + nj) * 8 + 2 * tig;
            if (j < EMB) {
                float b0 = __ldg(bias + j), b1 = __ldg(bias + j + 1);
                if (m < NNODES)
                    *(float2*)(g_hW + (size_t)m * EMB + j) =
                        make_float2(acc[mt][nj][0] + b0, acc[mt][nj][1] + b1);
                if (m + 8 < NNODES)
                    *(float2*)(g_hW + (size_t)(m + 8) * EMB + j) =
                        make_float2(acc[mt][nj][2] + b0, acc[mt][nj][3] + b1);
            }
        }
    }
}

// ---------------- aggregation + BN + relu -> A fragments (layers 0..3) ----------------
__global__ void __launch_bounds__(128) k_aggr_frag(int layer,
                                                   const float* __restrict__ rm,
                                                   const float* __restrict__ rv,
                                                   const float* __restrict__ gg,
                                                   const float* __restrict__ bb)
{
    __shared__ float hs[16][HSW];
    int tid = threadIdx.x, warp = tid >> 5, lane = tid & 31;
    int base = blockIdx.x * 16;
    const float4* ve4 = (const float4*)(g_ve_all + (size_t)layer * 2 * EMB);

    float4 e0[3], e1[3], bm[3], bv[3], bg[3], bbb[3];
#pragma unroll
    for (int i = 0; i < 3; i++) {
        int c = lane + 32 * i;
        if (c < EMB4) {
            e0[i] = __ldg(ve4 + c); e1[i] = __ldg(ve4 + EMB4 + c);
            bm[i] = __ldg((const float4*)rm + c);
            bv[i] = __ldg((const float4*)rv + c);
            bg[i] = __ldg((const float4*)gg + c);
            bbb[i] = __ldg((const float4*)bb + c);
        }
    }
#pragma unroll
    for (int ni = 0; ni < 4; ni++) {
        int row = warp * 4 + ni;
        int gw = base + row;
        float4 acc[3];
#pragma unroll
        for (int i = 0; i < 3; i++) acc[i] = make_float4(0.f, 0.f, 0.f, 0.f);
        int beg = g_off[gw], end = g_off[gw + 1];
        for (int e = beg; e < end; e++) {
            int src = g_csr_src[e];
            float2 ea = g_csr_ea[e];
            const float4* rowp = (const float4*)(g_hW + (size_t)src * EMB);
#pragma unroll
            for (int i = 0; i < 3; i++) {
                int c = lane + 32 * i;
                if (c < EMB4) {
                    float4 x = rowp[c];
                    acc[i].x += fmaxf(fmaf(ea.y, e1[i].x, fmaf(ea.x, e0[i].x, x.x)), 0.f);
                    acc[i].y += fmaxf(fmaf(ea.y, e1[i].y, fmaf(ea.x, e0[i].y, x.y)), 0.f);
                    acc[i].z += fmaxf(fmaf(ea.y, e1[i].z, fmaf(ea.x, e0[i].z, x.z)), 0.f);
                    acc[i].w += fmaxf(fmaf(ea.y, e1[i].w, fmaf(ea.x, e0[i].w, x.w)), 0.f);
                }
            }
        }
#pragma unroll
        for (int i = 0; i < 3; i++) {
            int c = lane + 32 * i;
            if (c < EMB4) {
                float4 y;
                y.x = fmaxf((acc[i].x - bm[i].x) * rsqrtf(bv[i].x + 1e-5f) * bg[i].x + bbb[i].x, 0.f);
                y.y = fmaxf((acc[i].y - bm[i].y) * rsqrtf(bv[i].y + 1e-5f) * bg[i].y + bbb[i].y, 0.f);
                y.z = fmaxf((acc[i].z - bm[i].z) * rsqrtf(bv[i].z + 1e-5f) * bg[i].z + bbb[i].z, 0.f);
                y.w = fmaxf((acc[i].w - bm[i].w) * rsqrtf(bv[i].w + 1e-5f) * bg[i].w + bbb[i].w, 0.f);
                *(float4*)&hs[row][4 * c] = y;
            }
        }
        hs[row][300 + lane] = 0.f;
    }
    __syncthreads();
    write_frags_from_smem(hs, blockIdx.x, warp, lane);
}

// ---------------- last layer aggregation + BN (no relu) -> g_h linear ----------------
__global__ void __launch_bounds__(256) k_aggr_last(int layer,
                                                   const float* __restrict__ rm,
                                                   const float* __restrict__ rv,
                                                   const float* __restrict__ gg,
                                                   const float* __restrict__ bb)
{
    int gw = (blockIdx.x * blockDim.x + threadIdx.x) >> 5;
    if (gw >= NNODES) return;
    int lane = threadIdx.x & 31;
    const float4* ve4 = (const float4*)(g_ve_all + (size_t)layer * 2 * EMB);

    float4 acc[3], e0[3], e1[3];
#pragma unroll
    for (int i = 0; i < 3; i++) {
        acc[i] = make_float4(0.f, 0.f, 0.f, 0.f);
        int c = lane + 32 * i;
        if (c < EMB4) { e0[i] = __ldg(ve4 + c); e1[i] = __ldg(ve4 + EMB4 + c); }
    }
    int beg = g_off[gw], end = g_off[gw + 1];
    for (int e = beg; e < end; e++) {
        int src = g_csr_src[e];
        float2 ea = g_csr_ea[e];
        const float4* row = (const float4*)(g_hW + (size_t)src * EMB);
#pragma unroll
        for (int i = 0; i < 3; i++) {
            int c = lane + 32 * i;
            if (c < EMB4) {
                float4 x = row[c];
                acc[i].x += fmaxf(fmaf(ea.y, e1[i].x, fmaf(ea.x, e0[i].x, x.x)), 0.f);
                acc[i].y += fmaxf(fmaf(ea.y, e1[i].y, fmaf(ea.x, e0[i].y, x.y)), 0.f);
                acc[i].z += fmaxf(fmaf(ea.y, e1[i].z, fmaf(ea.x, e0[i].z, x.z)), 0.f);
                acc[i].w += fmaxf(fmaf(ea.y, e1[i].w, fmaf(ea.x, e0[i].w, x.w)), 0.f);
            }
        }
    }
#pragma unroll
    for (int i = 0; i < 3; i++) {
        int c = lane + 32 * i;
        if (c < EMB4) {
            float4 m = __ldg((const float4*)rm + c);
            float4 v = __ldg((const float4*)rv + c);
            float4 g4 = __ldg((const float4*)gg + c);
            float4 b4 = __ldg((const float4*)bb + c);
            float4 y;
            y.x = (acc[i].x - m.x) * rsqrtf(v.x + 1e-5f) * g4.x + b4.x;
            y.y = (acc[i].y - m.y) * rsqrtf(v.y + 1e-5f) * g4.y + b4.y;
            y.z = (acc[i].z - m.z) * rsqrtf(v.z + 1e-5f) * g4.z + b4.z;
            y.w = (acc[i].w - m.w) * rsqrtf(v.w + 1e-5f) * g4.w + b4.w;
            ((float4*)(g_h + (size_t)gw * EMB))[c] = y;
        }
    }
}

// ---------------- readout ----------------
__global__ void k_q()
{
    __shared__ float mfs[4][EMB];
    int b0 = blockIdx.x * 4, tid = threadIdx.x;
    for (int i = tid; i < 4 * EMB; i += 256)
        mfs[i / EMB][i % EMB] = g_mf[(size_t)(b0 + i / EMB) * EMB + i % EMB];
    __syncthreads();
    float acc[4] = {0.f, 0.f, 0.f, 0.f};
    for (int j = 0; j < EMB; j++) {
        float w = g_wqt[(size_t)j * DK + tid];
#pragma unroll
        for (int g = 0; g < 4; g++) acc[g] = fmaf(mfs[g][j], w, acc[g]);
    }
#pragma unroll
    for (int g = 0; g < 4; g++) g_Q[(size_t)(b0 + g) * DK + tid] = acc[g];
}

__global__ void k_qk(const float* __restrict__ wk)
{
    __shared__ float Qs[4][DK];
    int b0 = blockIdx.x * 4, tid = threadIdx.x;
    for (int i = tid; i < 4 * DK; i += 320)
        Qs[i / DK][i % DK] = g_Q[(size_t)(b0 + i / DK) * DK + i % DK];
    __syncthreads();
    if (tid < EMB) {
        float acc[4] = {0.f, 0.f, 0.f, 0.f};
        for (int d = 0; d < DK; d++) {
            float w = __ldg(wk + (size_t)d * EMB + tid);
#pragma unroll
            for (int g = 0; g < 4; g++) acc[g] = fmaf(Qs[g][d], w, acc[g]);
        }
#pragma unroll
        for (int g = 0; g < 4; g++) g_qk[(size_t)(b0 + g) * EMB + tid] = acc[g];
    }
}

__global__ void k_attn()
{
    __shared__ float qks[EMB];
    __shared__ float sc[NPER];
    __shared__ float p[NPER];
    int b = blockIdx.x, tid = threadIdx.x;
    for (int i = tid; i < EMB; i += 256) qks[i] = g_qk[(size_t)b * EMB + i];
    __syncthreads();
    int warp = tid >> 5, lane = tid & 31;
    const float* hb = g_h + (size_t)b * NPER * EMB;
    for (int k = warp; k < NPER; k += 8) {
        float s = 0.f;
        for (int i = lane; i < EMB; i += 32) s = fmaf(qks[i], hb[(size_t)k * EMB + i], s);
#pragma unroll
        for (int off = 16; off; off >>= 1) s += __shfl_xor_sync(0xffffffffu, s, off);
        if (lane == 0) sc[k] = s * (1.0f / 16.0f);
    }
    __syncthreads();
    if (tid == 0) {
        float mx = -1e30f;
        for (int k = 0; k < NPER; k++) mx = fmaxf(mx, sc[k]);
        float ssum = 0.f;
        for (int k = 0; k < NPER; k++) { float e = expf(sc[k] - mx); p[k] = e; ssum += e; }
        float inv = 1.f / ssum;
        for (int k = 0; k < NPER; k++) p[k] *= inv;
    }
    __syncthreads();
    for (int j = tid; j < EMB; j += 256) {
        float ws = 0.f, mn = 0.f;
        for (int k = 0; k < NPER; k++) {
            float v = hb[(size_t)k * EMB + j];
            ws = fmaf(p[k], v, ws); mn += v;
        }
        g_wsum[(size_t)b * EMB + j] = ws;
        g_mean[(size_t)b * EMB + j] = mn * (1.0f / NPER);
    }
}

__global__ void k_final(const float* __restrict__ ml_b, const float* __restrict__ lg_b,
                        const float* __restrict__ ph1_b, const float* __restrict__ ph2_w,
                        const float* __restrict__ ph2_b, float* __restrict__ out)
{
    __shared__ float ws[4][EMB], mfs[4][EMB], mns[4][EMB];
    __shared__ float feat[4][DK];
    __shared__ float red[256];
    int b0 = blockIdx.x * 4, tid = threadIdx.x;
    for (int i = tid; i < 4 * EMB; i += 256) {
        int g = i / EMB, j = i % EMB;
        ws[g][j]  = g_wsum[(size_t)(b0 + g) * EMB + j];
        mfs[g][j] = g_mf[(size_t)(b0 + g) * EMB + j];
        mns[g][j] = g_mean[(size_t)(b0 + g) * EMB + j];
    }
    __syncthreads();
    int d = tid;
    float a[4], m2[4], lg[4];
    float mb = __ldg(ml_b + d), lb = __ldg(lg_b + d);
#pragma unroll
    for (int g = 0; g < 4; g++) { a[g] = 0.f; m2[g] = mb; lg[g] = lb; }
    for (int k = 0; k < EMB; k++) {
        float wv_ = g_wvt[(size_t)k * DK + d];
        float ml_ = g_mlt[(size_t)k * DK + d];
        float lg_ = g_lgt[(size_t)k * DK + d];
#pragma unroll
        for (int g = 0; g < 4; g++) {
            a[g]  = fmaf(wv_, ws[g][k],  a[g]);
            m2[g] = fmaf(ml_, mfs[g][k], m2[g]);
            lg[g] = fmaf(lg_, mns[g][k], lg[g]);
        }
    }
#pragma unroll
    for (int g = 0; g < 4; g++)
        feat[g][d] = fmaxf(a[g], 0.f) + fmaxf(m2[g], 0.f) + fmaxf(lg[g], 0.f);
    __syncthreads();
    float part[4] = {0.f, 0.f, 0.f, 0.f};
#pragma unroll
    for (int rep = 0; rep < 2; rep++) {
        int o = tid + rep * 256;
        float t[4];
        float pb = __ldg(ph1_b + o);
#pragma unroll
        for (int g = 0; g < 4; g++) t[g] = pb;
        for (int k = 0; k < DK; k++) {
            float w = g_ph1t[(size_t)k * 512 + o];
#pragma unroll
            for (int g = 0; g < 4; g++) t[g] = fmaf(w, feat[g][k], t[g]);
        }
        float p2 = __ldg(ph2_w + o);
#pragma unroll
        for (int g = 0; g < 4; g++) {
            float x = t[g];
            float sp = (x > 20.f) ? x : log1pf(expf(x));
            part[g] = fmaf(sp, p2, part[g]);
        }
    }
    for (int g = 0; g < 4; g++) {
        red[tid] = part[g];
        __syncthreads();
        for (int s = 128; s; s >>= 1) {
            if (tid < s) red[tid] += red[tid + s];
            __syncthreads();
        }
        if (tid == 0) out[b0 + g] = red[0] + __ldg(ph2_b);
        __syncthreads();
    }
}

// ---------------- launch ----------------
extern "C" void kernel_launch(void* const* d_in, const int* in_sizes, int n_in,
                              void* d_out, int out_size)
{
    const int*   x_type     = (const int*)d_in[0];
    const float* x_feat     = (const float*)d_in[1];
    const int*   edge_index = (const int*)d_in[2];
    const float* edge_attr  = (const float*)d_in[3];
    const int*   metal_type = (const int*)d_in[4];
    const float* metal_feat = (const float*)d_in[5];
    const float* x_emb      = (const float*)d_in[6];
    const float* x_weight   = (const float*)d_in[7];
    const float* ew1        = (const float*)d_in[8];
    const float* mlp_w      = (const float*)d_in[9];
    const float* mlp_b      = (const float*)d_in[10];
    const float* bn_g       = (const float*)d_in[11];
    const float* bn_b       = (const float*)d_in[12];
    const float* bn_rm      = (const float*)d_in[13];
    const float* bn_rv      = (const float*)d_in[14];
    const float* me1_w      = (const float*)d_in[15];
    const float* me1_b      = (const float*)d_in[16];
    const float* me2        = (const float*)d_in[17];
    const float* wq         = (const float*)d_in[18];
    const float* wk         = (const float*)d_in[19];
    const float* wv         = (const float*)d_in[20];
    const float* ml_w       = (const float*)d_in[21];
    const float* ml_b       = (const float*)d_in[22];
    const float* lg_w       = (const float*)d_in[23];
    const float* lg_b       = (const float*)d_in[24];
    const float* ph1_w      = (const float*)d_in[25];
    const float* ph1_b      = (const float*)d_in[26];
    const float* ph2_w      = (const float*)d_in[27];
    const float* ph2_b      = (const float*)d_in[28];
    float* out = (float*)d_out;

    k_init_frag<<<NNODES / 16, 128>>>(x_type, x_feat, x_emb, x_weight);
    k_wsplit_frag<<<(NLAYERS * NNT * NKT * 32 + 255) / 256, 256>>>(mlp_w);
    k_mf<<<(BGR * EMB + 255) / 256, 256>>>(metal_type, metal_feat, me1_w, me1_b, me2);
    k_transpose_all<<<(4 * DK * EMB + 512 * DK + 255) / 256, 256>>>(wq, wv, ml_w, lg_w, ph1_w);
    k_ve_all<<<(NLAYERS * 2 * EMB * 32 + 255) / 256, 256>>>(ew1, mlp_w);

    // CSR build (once per launch)
    k_deg_init<<<(NNODES + 255) / 256, 256>>>();
    k_deg_count<<<(NEDGES + 255) / 256, 256>>>(edge_index);
    k_scan<<<1, 1024>>>();
    k_fill<<<(TOTE + 255) / 256, 256>>>(edge_index, edge_attr);

    dim3 gg(NPADM / 128, 2);
    for (int l = 0; l < NLAYERS; l++) {
        k_gemm_frag<<<gg, 256>>>(l, mlp_b + (size_t)l * EMB);
        if (l < NLAYERS - 1)
            k_aggr_frag<<<NNODES / 16, 128>>>(
                l, bn_rm + (size_t)l * EMB, bn_rv + (size_t)l * EMB,
                bn_g + (size_t)l * EMB, bn_b + (size_t)l * EMB);
        else
            k_aggr_last<<<(NNODES * 32 + 255) / 256, 256>>>(
                l, bn_rm + (size_t)l * EMB, bn_rv + (size_t)l * EMB,
                bn_g + (size_t)l * EMB, bn_b + (size_t)l * EMB);
    }

    k_q<<<BGR / 4, 256>>>();
    k_qk<<<BGR / 4, 320>>>(wk);
    k_attn<<<BGR, 256>>>();
    k_final<<<BGR / 4, 256>>>(ml_b, lg_b, ph1_b, ph2_w, ph2_b, out);
}

// round 8
// speedup vs baseline: 1.2029x; 1.2029x over previous
#include <cuda_runtime.h>
#include <cuda_bf16.h>
#include <math.h>
#include <stdint.h>

#define NNODES 50000
#define NPADM  50048
#define NMCH   391         // 128-row m-chunks (NPADM/128)
#define NEDGES 200000
#define TOTE   (NEDGES + NNODES)
#define EMB    300
#define EMB4   75
#define KPAD   320
#define NKT    20          // KPAD/16
#define DK     256
#define BGR    1000
#define NPER   50
#define NLAYERS 5
#define PADF   16
#define GRIDX  74

// ---------------- scratch (device globals) ----------------
__device__ float g_h[NNODES * EMB];
__device__ float g_hW[NNODES * EMB];
// A fragments: [mchunk(391)][kt(20)][mt8(8)][lane(32)] uint4  (4KB contiguous per (mchunk,kt))
__device__ uint4 g_hfa_hi[NMCH * NKT * 8 * 32];
__device__ uint4 g_hfa_lo[NMCH * NKT * 8 * 32];
// B fragments: [layer][jblk(2)][ntl(20)][kt(20)][lane(32)] uint4 {b0h,b1h,b0l,b1l}
__device__ uint4 g_wfb[NLAYERS * 2 * 20 * NKT * 32];
__device__ float g_mf[BGR * EMB];
__device__ float g_ve_all[NLAYERS * 2 * EMB];
__device__ float g_Q[BGR * DK];
__device__ float g_qk[BGR * EMB];
__device__ float g_wsum[BGR * EMB];
__device__ float g_mean[BGR * EMB];
__device__ float g_wqt[EMB * DK];
__device__ float g_wvt[EMB * DK];
__device__ float g_mlt[EMB * DK];
__device__ float g_lgt[EMB * DK];
__device__ float g_ph1t[DK * 512];
// CSR
__device__ int g_deg[NNODES];
__device__ int g_off[NNODES + 1];
__device__ int g_cur[NNODES];
__device__ int g_csr_src[TOTE];
__device__ float2 g_csr_ea[TOTE];

// ---------------- helpers ----------------
__device__ __forceinline__ void split_pack(float v0, float v1, uint32_t& hi, uint32_t& lo)
{
    __nv_bfloat16 h0 = __float2bfloat16(v0);
    __nv_bfloat16 h1 = __float2bfloat16(v1);
    __nv_bfloat16 l0 = __float2bfloat16(v0 - __bfloat162float(h0));
    __nv_bfloat16 l1 = __float2bfloat16(v1 - __bfloat162float(h1));
    __nv_bfloat162 H = __halves2bfloat162(h0, h1);
    __nv_bfloat162 L = __halves2bfloat162(l0, l1);
    hi = *(uint32_t*)&H;
    lo = *(uint32_t*)&L;
}

__device__ __forceinline__ uint32_t smem_u32(const void* p) {
    uint32_t a;
    asm("{ .reg .u64 t; cvta.to.shared.u64 t, %1; cvt.u32.u64 %0, t; }" : "=r"(a) : "l"(p));
    return a;
}

#define MMA_BF16(d, a, b) asm volatile( \
    "mma.sync.aligned.m16n8k16.row.col.f32.bf16.bf16.f32 " \
    "{%0,%1,%2,%3},{%4,%5,%6,%7},{%8,%9},{%0,%1,%2,%3};\n" \
    : "+f"(d[0]), "+f"(d[1]), "+f"(d[2]), "+f"(d[3]) \
    : "r"((a)[0]), "r"((a)[1]), "r"((a)[2]), "r"((a)[3]), "r"((b)[0]), "r"((b)[1]))

#define LDS128(r, a) asm volatile( \
    "ld.shared.v4.b32 {%0,%1,%2,%3}, [%4];" \
    : "=r"((r)[0]), "=r"((r)[1]), "=r"((r)[2]), "=r"((r)[3]) : "r"(a))

#define MB_INIT(m) asm volatile("mbarrier.init.shared.b64 [%0], %1;" \
    :: "r"(m), "r"(1u) : "memory")
#define MB_EXPECT(m, n) asm volatile("mbarrier.arrive.expect_tx.shared.b64 _, [%0], %1;" \
    :: "r"(m), "r"((uint32_t)(n)) : "memory")
#define BULK_G2S(dst, src, sz, m) asm volatile( \
    "cp.async.bulk.shared::cluster.global.mbarrier::complete_tx::bytes [%0], [%1], %2, [%3];" \
    :: "r"(dst), "l"(src), "r"((uint32_t)(sz)), "r"(m) : "memory")

__device__ __forceinline__ void mbar_wait(uint32_t addr, uint32_t parity)
{
    uint32_t done;
    do {
        asm volatile(
            "{\n\t.reg .pred p;\n\t"
            "mbarrier.try_wait.parity.acquire.cta.shared::cta.b64 p, [%1], %2, 0x989680;\n\t"
            "selp.b32 %0,1,0,p;\n\t}"
            : "=r"(done) : "r"(addr), "r"(parity) : "memory");
    } while (!done);
}

// shared fragment-writer: block covers 16 node rows in hs[16][HSW], writes A frags (8 warps)
#define HSW 332
__device__ __forceinline__ void write_frags_from_smem(float (*hs)[HSW], int mtile,
                                                      int warp, int lane)
{
    int gid = lane >> 2, tig = lane & 3;
    int mc = mtile >> 3, mt8 = mtile & 7;
    for (int kt = warp; kt < NKT; kt += 8) {
        int kb = kt * 16;
        float v00 = hs[gid][kb + 2 * tig],     v01 = hs[gid][kb + 2 * tig + 1];
        float v10 = hs[gid + 8][kb + 2 * tig], v11 = hs[gid + 8][kb + 2 * tig + 1];
        float v20 = hs[gid][kb + 8 + 2 * tig],     v21 = hs[gid][kb + 8 + 2 * tig + 1];
        float v30 = hs[gid + 8][kb + 8 + 2 * tig], v31 = hs[gid + 8][kb + 8 + 2 * tig + 1];
        uint4 Hi, Lo;
        split_pack(v00, v01, Hi.x, Lo.x);
        split_pack(v10, v11, Hi.y, Lo.y);
        split_pack(v20, v21, Hi.z, Lo.z);
        split_pack(v30, v31, Hi.w, Lo.w);
        size_t idx = (((size_t)mc * NKT + kt) * 8 + mt8) * 32 + lane;
        g_hfa_hi[idx] = Hi;
        g_hfa_lo[idx] = Lo;
    }
}

// ---------------- node init -> A fragments ----------------
__global__ void __launch_bounds__(256) k_init_frag(const int* __restrict__ x_type,
                                                   const float* __restrict__ x_feat,
                                                   const float* __restrict__ x_emb,
                                                   const float* __restrict__ x_weight)
{
    __shared__ float hs[16][HSW];
    int tid = threadIdx.x, warp = tid >> 5, lane = tid & 31;
    int base = blockIdx.x * 16;
#pragma unroll
    for (int i = 0; i < 2; i++) {
        int row = warp * 2 + i;
        int n = base + row;
        int t = __ldg(x_type + n);
#pragma unroll
        for (int ch = 0; ch < 3; ch++) {
            int c = lane + 32 * ch;
            if (c < EMB4) {
                float4 acc = __ldg((const float4*)(x_emb + (size_t)t * EMB) + c);
#pragma unroll
                for (int k = 0; k < PADF; k++) {
                    float f = __ldg(x_feat + (size_t)n * PADF + k);
                    float4 w = __ldg((const float4*)(x_weight + (size_t)k * EMB) + c);
                    acc.x = fmaf(f, w.x, acc.x); acc.y = fmaf(f, w.y, acc.y);
                    acc.z = fmaf(f, w.z, acc.z); acc.w = fmaf(f, w.w, acc.w);
                }
                *(float4*)&hs[row][4 * c] = acc;
            }
        }
        hs[row][300 + lane] = 0.f;   // zero pad cols 300..331
    }
    __syncthreads();
    write_frags_from_smem(hs, blockIdx.x, warp, lane);
}

// ---------------- weight split -> B fragments (all layers, once) ----------------
__global__ void k_wsplit_frag(const float* __restrict__ mlp_w)
{
    int idx = blockIdx.x * blockDim.x + threadIdx.x;
    if (idx >= NLAYERS * 2 * 20 * NKT * 32) return;
    int lane = idx & 31;
    int kt = (idx >> 5) % NKT;
    int ntl = (idx >> 5) / NKT % 20;
    int jblk = (idx >> 5) / (NKT * 20) % 2;
    int l = idx / (32 * NKT * 20 * 2);
    int gid = lane >> 2, tig = lane & 3;
    int j = jblk * 160 + ntl * 8 + gid;
    int k0 = kt * 16 + 2 * tig;
    int k1 = k0 + 8;
    const float* W = mlp_w + (size_t)l * EMB * EMB + (size_t)j * EMB;
    float w00 = (j < EMB && k0 < EMB) ? __ldg(W + k0) : 0.f;
    float w01 = (j < EMB && k0 + 1 < EMB) ? __ldg(W + k0 + 1) : 0.f;
    float w10 = (j < EMB && k1 < EMB) ? __ldg(W + k1) : 0.f;
    float w11 = (j < EMB && k1 + 1 < EMB) ? __ldg(W + k1 + 1) : 0.f;
    uint4 o;
    split_pack(w00, w01, o.x, o.z);
    split_pack(w10, w11, o.y, o.w);
    g_wfb[idx] = o;
}

// ---------------- metal feature ----------------
__global__ void k_mf(const int* __restrict__ metal_type, const float* __restrict__ metal_feat,
                     const float* __restrict__ me1_w, const float* __restrict__ me1_b,
                     const float* __restrict__ me2)
{
    int idx = blockIdx.x * blockDim.x + threadIdx.x;
    if (idx >= BGR * EMB) return;
    int b = idx / EMB, j = idx % EMB;
    float acc = __ldg(me1_b + j) + __ldg(me2 + (size_t)__ldg(metal_type + b) * EMB + j);
#pragma unroll
    for (int k = 0; k < 17; k++)
        acc = fmaf(__ldg(metal_feat + (size_t)b * 17 + k), __ldg(me1_w + (size_t)j * 17 + k), acc);
    g_mf[idx] = acc;
}

// ---------------- transpose readout weights ----------------
__global__ void k_transpose_all(const float* __restrict__ wq, const float* __restrict__ wv,
                                const float* __restrict__ ml, const float* __restrict__ lg,
                                const float* __restrict__ ph1)
{
    int idx = blockIdx.x * blockDim.x + threadIdx.x;
    const int SZ1 = DK * EMB;
    if (idx < 4 * SZ1) {
        int w = idx / SZ1, i = idx % SZ1;
        int d = i / EMB, j = i % EMB;
        float v = (w == 0) ? wq[i] : (w == 1) ? wv[i] : (w == 2) ? ml[i] : lg[i];
        float* dst = (w == 0) ? g_wqt : (w == 1) ? g_wvt : (w == 2) ? g_mlt : g_lgt;
        dst[(size_t)j * DK + d] = v;
    } else {
        int i = idx - 4 * SZ1;
        if (i < 512 * DK) {
            int o = i / DK, d = i % DK;
            g_ph1t[(size_t)d * 512 + o] = ph1[i];
        }
    }
}

// ---------------- all layers' edge vectors ----------------
__global__ void k_ve_all(const float* __restrict__ ew1, const float* __restrict__ mlp_w)
{
    int o = (blockIdx.x * blockDim.x + threadIdx.x) >> 5;
    if (o >= NLAYERS * 2 * EMB) return;
    int lane = threadIdx.x & 31;
    int l = o / (2 * EMB);
    int rem = o % (2 * EMB);
    int w = rem / EMB, col = rem % EMB;
    const float* e = ew1 + (size_t)l * 2 * EMB + (size_t)w * EMB;
    const float* wr = mlp_w + (size_t)l * EMB * EMB + (size_t)col * EMB;
    float s = 0.f;
    for (int k = lane; k < EMB; k += 32) s = fmaf(__ldg(e + k), __ldg(wr + k), s);
#pragma unroll
    for (int off = 16; off; off >>= 1) s += __shfl_xor_sync(0xffffffffu, s, off);
    if (lane == 0) g_ve_all[o] = s;
}

// ---------------- CSR build ----------------
__global__ void k_deg_init() {
    int i = blockIdx.x * blockDim.x + threadIdx.x;
    if (i < NNODES) g_deg[i] = 1;
}
__global__ void k_deg_count(const int* __restrict__ eidx) {
    int e = blockIdx.x * blockDim.x + threadIdx.x;
    if (e < NEDGES) atomicAdd(&g_deg[__ldg(eidx + NEDGES + e)], 1);
}
__global__ void k_scan() {
    __shared__ int ps[1024];
    const int C = (NNODES + 1023) / 1024;
    int t = threadIdx.x;
    int base = t * C;
    int s = 0;
    for (int i = base; i < base + C && i < NNODES; i++) s += g_deg[i];
    ps[t] = s;
    __syncthreads();
    for (int off = 1; off < 1024; off <<= 1) {
        int v = (t >= off) ? ps[t - off] : 0;
        __syncthreads();
        ps[t] += v;
        __syncthreads();
    }
    int ex = (t == 0) ? 0 : ps[t - 1];
    for (int i = base; i < base + C && i < NNODES; i++) {
        g_off[i] = ex; g_cur[i] = ex;
        ex += g_deg[i];
    }
    if (t == 1023) g_off[NNODES] = TOTE;
}
__global__ void k_fill(const int* __restrict__ eidx, const float* __restrict__ eattr) {
    int idx = blockIdx.x * blockDim.x + threadIdx.x;
    if (idx >= TOTE) return;
    int src, col; float2 ea;
    if (idx < NEDGES) {
        src = __ldg(eidx + idx);
        col = __ldg(eidx + NEDGES + idx);
        ea = __ldg((const float2*)eattr + idx);
    } else {
        src = col = idx - NEDGES;
        ea = make_float2(0.f, 4.f);
    }
    int pos = atomicAdd(&g_cur[col], 1);
    g_csr_src[pos] = src;
    g_csr_ea[pos] = ea;
}

// ---------------- GEMM: persistent CTAs, B resident in smem, A bulk-streamed ------
// grid (74, 2); 256 thr = warps 4(M) x 2(N); CTA tile 128 x 160; K = 320 (20 kt).
// smem: B frags @0 (204800B), A double buf @204800 (2 x 8192), mbarriers @221184.
#define BSM_A   204800
#define ABUF_SZ 8192
#define BSM_MB  221184
#define GEMM_SMEM 221248

__global__ void __launch_bounds__(256) k_gemm_bulk(int layer, const float* __restrict__ bias)
{
    extern __shared__ char smem[];
    uint32_t sb = smem_u32(smem);
    int tid = threadIdx.x, warp = tid >> 5, lane = tid & 31;
    int gid = lane >> 2, tig = lane & 3;
    int wm = warp & 3, wn = warp >> 2;     // 4(M) x 2(N)
    int jblk = blockIdx.y;
    uint32_t mb_b = sb + BSM_MB;
    uint32_t mb_a[2] = {sb + BSM_MB + 8, sb + BSM_MB + 16};

    if (tid == 0) { MB_INIT(mb_b); MB_INIT(mb_a[0]); MB_INIT(mb_a[1]); }
    __syncthreads();

    int mc0 = blockIdx.x;
    if (tid == 0) {
        const char* Bsrc = (const char*)(g_wfb + ((size_t)layer * 2 + jblk) * (20 * NKT * 32));
        MB_EXPECT(mb_b, 204800);
        BULK_G2S(sb, Bsrc, 204800, mb_b);
        MB_EXPECT(mb_a[0], 2 * 4096);
        BULK_G2S(sb + BSM_A, (const char*)(g_hfa_hi + (size_t)mc0 * NKT * 256), 4096, mb_a[0]);
        BULK_G2S(sb + BSM_A + 4096, (const char*)(g_hfa_lo + (size_t)mc0 * NKT * 256), 4096, mb_a[0]);
    }
    int phA[2] = {0, 0};
    mbar_wait(mb_b, 0);

    for (int mc = mc0; mc < NMCH; mc += GRIDX) {
        float acc[2][10][4];
#pragma unroll
        for (int mt = 0; mt < 2; mt++)
#pragma unroll
            for (int nj = 0; nj < 10; nj++)
#pragma unroll
                for (int r = 0; r < 4; r++) acc[mt][nj][r] = 0.f;

        for (int kt = 0; kt < NKT; kt++) {
            int buf = kt & 1;
            mbar_wait(mb_a[buf], phA[buf]);
            phA[buf] ^= 1;
            if (tid == 0 && kt < NKT - 1) {
                uint32_t dst = sb + BSM_A + (1 - buf) * ABUF_SZ;
                size_t so = ((size_t)mc * NKT + kt + 1) * 256;
                MB_EXPECT(mb_a[1 - buf], 2 * 4096);
                BULK_G2S(dst, (const char*)(g_hfa_hi + so), 4096, mb_a[1 - buf]);
                BULK_G2S(dst + 4096, (const char*)(g_hfa_lo + so), 4096, mb_a[1 - buf]);
            }
            uint32_t Ab = sb + BSM_A + buf * ABUF_SZ;
            uint32_t ah[2][4], al[2][4], bq[10][4];
#pragma unroll
            for (int mt = 0; mt < 2; mt++) {
                uint32_t ao = ((uint32_t)(wm * 2 + mt) * 32 + lane) * 16;
                LDS128(ah[mt], Ab + ao);
                LDS128(al[mt], Ab + 4096 + ao);
            }
#pragma unroll
            for (int nj = 0; nj < 10; nj++) {
                uint32_t bo = (((uint32_t)(wn * 10 + nj) * NKT + kt) * 32 + lane) * 16;
                LDS128(bq[nj], sb + bo);
            }
#pragma unroll
            for (int mt = 0; mt < 2; mt++)
#pragma unroll
                for (int nj = 0; nj < 10; nj++) MMA_BF16(acc[mt][nj], ah[mt], bq[nj]);
#pragma unroll
            for (int mt = 0; mt < 2; mt++)
#pragma unroll
                for (int nj = 0; nj < 10; nj++) MMA_BF16(acc[mt][nj], al[mt], bq[nj]);
#pragma unroll
            for (int mt = 0; mt < 2; mt++)
#pragma unroll
                for (int nj = 0; nj < 10; nj++) MMA_BF16(acc[mt][nj], ah[mt], bq[nj] + 2);
            __syncthreads();
        }
        // prefetch next m-chunk's kt=0 into buf 0 (free: last used kt=18, synced)
        if (tid == 0 && mc + GRIDX < NMCH) {
            size_t so = (size_t)(mc + GRIDX) * NKT * 256;
            MB_EXPECT(mb_a[0], 2 * 4096);
            BULK_G2S(sb + BSM_A, (const char*)(g_hfa_hi + so), 4096, mb_a[0]);
            BULK_G2S(sb + BSM_A + 4096, (const char*)(g_hfa_lo + so), 4096, mb_a[0]);
        }
        // epilogue
#pragma unroll
        for (int mt = 0; mt < 2; mt++) {
            int m = mc * 128 + (wm * 2 + mt) * 16 + gid;
#pragma unroll
            for (int nj = 0; nj < 10; nj++) {
                int j = jblk * 160 + (wn * 10 + nj) * 8 + 2 * tig;
                if (j < EMB) {
                    float b0 = __ldg(bias + j), b1 = __ldg(bias + j + 1);
                    if (m < NNODES)
                        *(float2*)(g_hW + (size_t)m * EMB + j) =
                            make_float2(acc[mt][nj][0] + b0, acc[mt][nj][1] + b1);
                    if (m + 8 < NNODES)
                        *(float2*)(g_hW + (size_t)(m + 8) * EMB + j) =
                            make_float2(acc[mt][nj][2] + b0, acc[mt][nj][3] + b1);
                }
            }
        }
    }
}

// ---------------- aggregation + BN + relu -> A fragments (layers 0..3) ----------------
__global__ void __launch_bounds__(256) k_aggr_frag(int layer,
                                                   const float* __restrict__ rm,
                                                   const float* __restrict__ rv,
                                                   const float* __restrict__ gg,
                                                   const float* __restrict__ bb)
{
    __shared__ float hs[16][HSW];
    int tid = threadIdx.x, warp = tid >> 5, lane = tid & 31;
    int base = blockIdx.x * 16;
    const float4* ve4 = (const float4*)(g_ve_all + (size_t)layer * 2 * EMB);

    float4 e0[3], e1[3], bm[3], bv[3], bg[3], bbb[3];
#pragma unroll
    for (int i = 0; i < 3; i++) {
        int c = lane + 32 * i;
        if (c < EMB4) {
            e0[i] = __ldg(ve4 + c); e1[i] = __ldg(ve4 + EMB4 + c);
            bm[i] = __ldg((const float4*)rm + c);
            bv[i] = __ldg((const float4*)rv + c);
            bg[i] = __ldg((const float4*)gg + c);
            bbb[i] = __ldg((const float4*)bb + c);
        }
    }
#pragma unroll
    for (int ni = 0; ni < 2; ni++) {
        int row = warp * 2 + ni;
        int gw = base + row;
        float4 acc[3];
#pragma unroll
        for (int i = 0; i < 3; i++) acc[i] = make_float4(0.f, 0.f, 0.f, 0.f);
        int beg = g_off[gw], end = g_off[gw + 1];
        for (int e = beg; e < end; e++) {
            int src = g_csr_src[e];
            float2 ea = g_csr_ea[e];
            const float4* rowp = (const float4*)(g_hW + (size_t)src * EMB);
#pragma unroll
            for (int i = 0; i < 3; i++) {
                int c = lane + 32 * i;
                if (c < EMB4) {
                    float4 x = rowp[c];
                    acc[i].x += fmaxf(fmaf(ea.y, e1[i].x, fmaf(ea.x, e0[i].x, x.x)), 0.f);
                    acc[i].y += fmaxf(fmaf(ea.y, e1[i].y, fmaf(ea.x, e0[i].y, x.y)), 0.f);
                    acc[i].z += fmaxf(fmaf(ea.y, e1[i].z, fmaf(ea.x, e0[i].z, x.z)), 0.f);
                    acc[i].w += fmaxf(fmaf(ea.y, e1[i].w, fmaf(ea.x, e0[i].w, x.w)), 0.f);
                }
            }
        }
#pragma unroll
        for (int i = 0; i < 3; i++) {
            int c = lane + 32 * i;
            if (c < EMB4) {
                float4 y;
                y.x = fmaxf((acc[i].x - bm[i].x) * rsqrtf(bv[i].x + 1e-5f) * bg[i].x + bbb[i].x, 0.f);
                y.y = fmaxf((acc[i].y - bm[i].y) * rsqrtf(bv[i].y + 1e-5f) * bg[i].y + bbb[i].y, 0.f);
                y.z = fmaxf((acc[i].z - bm[i].z) * rsqrtf(bv[i].z + 1e-5f) * bg[i].z + bbb[i].z, 0.f);
                y.w = fmaxf((acc[i].w - bm[i].w) * rsqrtf(bv[i].w + 1e-5f) * bg[i].w + bbb[i].w, 0.f);
                *(float4*)&hs[row][4 * c] = y;
            }
        }
        hs[row][300 + lane] = 0.f;
    }
    __syncthreads();
    write_frags_from_smem(hs, blockIdx.x, warp, lane);
}

// ---------------- last layer aggregation + BN (no relu) -> g_h linear ----------------
__global__ void __launch_bounds__(256) k_aggr_last(int layer,
                                                   const float* __restrict__ rm,
                                                   const float* __restrict__ rv,
                                                   const float* __restrict__ gg,
                                                   const float* __restrict__ bb)
{
    int gw = (blockIdx.x * blockDim.x + threadIdx.x) >> 5;
    if (gw >= NNODES) return;
    int lane = threadIdx.x & 31;
    const float4* ve4 = (const float4*)(g_ve_all + (size_t)layer * 2 * EMB);

    float4 acc[3], e0[3], e1[3];
#pragma unroll
    for (int i = 0; i < 3; i++) {
        acc[i] = make_float4(0.f, 0.f, 0.f, 0.f);
        int c = lane + 32 * i;
        if (c < EMB4) { e0[i] = __ldg(ve4 + c); e1[i] = __ldg(ve4 + EMB4 + c); }
    }
    int beg = g_off[gw], end = g_off[gw + 1];
    for (int e = beg; e < end; e++) {
        int src = g_csr_src[e];
        float2 ea = g_csr_ea[e];
        const float4* row = (const float4*)(g_hW + (size_t)src * EMB);
#pragma unroll
        for (int i = 0; i < 3; i++) {
            int c = lane + 32 * i;
            if (c < EMB4) {
                float4 x = row[c];
                acc[i].x += fmaxf(fmaf(ea.y, e1[i].x, fmaf(ea.x, e0[i].x, x.x)), 0.f);
                acc[i].y += fmaxf(fmaf(ea.y, e1[i].y, fmaf(ea.x, e0[i].y, x.y)), 0.f);
                acc[i].z += fmaxf(fmaf(ea.y, e1[i].z, fmaf(ea.x, e0[i].z, x.z)), 0.f);
                acc[i].w += fmaxf(fmaf(ea.y, e1[i].w, fmaf(ea.x, e0[i].w, x.w)), 0.f);
            }
        }
    }
#pragma unroll
    for (int i = 0; i < 3; i++) {
        int c = lane + 32 * i;
        if (c < EMB4) {
            float4 m = __ldg((const float4*)rm + c);
            float4 v = __ldg((const float4*)rv + c);
            float4 g4 = __ldg((const float4*)gg + c);
            float4 b4 = __ldg((const float4*)bb + c);
            float4 y;
            y.x = (acc[i].x - m.x) * rsqrtf(v.x + 1e-5f) * g4.x + b4.x;
            y.y = (acc[i].y - m.y) * rsqrtf(v.y + 1e-5f) * g4.y + b4.y;
            y.z = (acc[i].z - m.z) * rsqrtf(v.z + 1e-5f) * g4.z + b4.z;
            y.w = (acc[i].w - m.w) * rsqrtf(v.w + 1e-5f) * g4.w + b4.w;
            ((float4*)(g_h + (size_t)gw * EMB))[c] = y;
        }
    }
}

// ---------------- readout ----------------
__global__ void k_q()
{
    __shared__ float mfs[4][EMB];
    int b0 = blockIdx.x * 4, tid = threadIdx.x;
    for (int i = tid; i < 4 * EMB; i += 256)
        mfs[i / EMB][i % EMB] = g_mf[(size_t)(b0 + i / EMB) * EMB + i % EMB];
    __syncthreads();
    float acc[4] = {0.f, 0.f, 0.f, 0.f};
    for (int j = 0; j < EMB; j++) {
        float w = g_wqt[(size_t)j * DK + tid];
#pragma unroll
        for (int g = 0; g < 4; g++) acc[g] = fmaf(mfs[g][j], w, acc[g]);
    }
#pragma unroll
    for (int g = 0; g < 4; g++) g_Q[(size_t)(b0 + g) * DK + tid] = acc[g];
}

__global__ void k_qk(const float* __restrict__ wk)
{
    __shared__ float Qs[4][DK];
    int b0 = blockIdx.x * 4, tid = threadIdx.x;
    for (int i = tid; i < 4 * DK; i += 320)
        Qs[i / DK][i % DK] = g_Q[(size_t)(b0 + i / DK) * DK + i % DK];
    __syncthreads();
    if (tid < EMB) {
        float acc[4] = {0.f, 0.f, 0.f, 0.f};
        for (int d = 0; d < DK; d++) {
            float w = __ldg(wk + (size_t)d * EMB + tid);
#pragma unroll
            for (int g = 0; g < 4; g++) acc[g] = fmaf(Qs[g][d], w, acc[g]);
        }
#pragma unroll
        for (int g = 0; g < 4; g++) g_qk[(size_t)(b0 + g) * EMB + tid] = acc[g];
    }
}

__global__ void k_attn()
{
    __shared__ float qks[EMB];
    __shared__ float sc[NPER];
    __shared__ float p[NPER];
    int b = blockIdx.x, tid = threadIdx.x;
    for (int i = tid; i < EMB; i += 256) qks[i] = g_qk[(size_t)b * EMB + i];
    __syncthreads();
    int warp = tid >> 5, lane = tid & 31;
    const float* hb = g_h + (size_t)b * NPER * EMB;
    for (int k = warp; k < NPER; k += 8) {
        float s = 0.f;
        for (int i = lane; i < EMB; i += 32) s = fmaf(qks[i], hb[(size_t)k * EMB + i], s);
#pragma unroll
        for (int off = 16; off; off >>= 1) s += __shfl_xor_sync(0xffffffffu, s, off);
        if (lane == 0) sc[k] = s * (1.0f / 16.0f);
    }
    __syncthreads();
    if (tid == 0) {
        float mx = -1e30f;
        for (int k = 0; k < NPER; k++) mx = fmaxf(mx, sc[k]);
        float ssum = 0.f;
        for (int k = 0; k < NPER; k++) { float e = expf(sc[k] - mx); p[k] = e; ssum += e; }
        float inv = 1.f / ssum;
        for (int k = 0; k < NPER; k++) p[k] *= inv;
    }
    __syncthreads();
    for (int j = tid; j < EMB; j += 256) {
        float ws = 0.f, mn = 0.f;
        for (int k = 0; k < NPER; k++) {
            float v = hb[(size_t)k * EMB + j];
            ws = fmaf(p[k], v, ws); mn += v;
        }
        g_wsum[(size_t)b * EMB + j] = ws;
        g_mean[(size_t)b * EMB + j] = mn * (1.0f / NPER);
    }
}

__global__ void k_final(const float* __restrict__ ml_b, const float* __restrict__ lg_b,
                        const float* __restrict__ ph1_b, const float* __restrict__ ph2_w,
                        const float* __restrict__ ph2_b, float* __restrict__ out)
{
    __shared__ float ws[4][EMB], mfs[4][EMB], mns[4][EMB];
    __shared__ float feat[4][DK];
    __shared__ float red[256];
    int b0 = blockIdx.x * 4, tid = threadIdx.x;
    for (int i = tid; i < 4 * EMB; i += 256) {
        int g = i / EMB, j = i % EMB;
        ws[g][j]  = g_wsum[(size_t)(b0 + g) * EMB + j];
        mfs[g][j] = g_mf[(size_t)(b0 + g) * EMB + j];
        mns[g][j] = g_mean[(size_t)(b0 + g) * EMB + j];
    }
    __syncthreads();
    int d = tid;
    float a[4], m2[4], lg[4];
    float mb = __ldg(ml_b + d), lb = __ldg(lg_b + d);
#pragma unroll
    for (int g = 0; g < 4; g++) { a[g] = 0.f; m2[g] = mb; lg[g] = lb; }
    for (int k = 0; k < EMB; k++) {
        float wv_ = g_wvt[(size_t)k * DK + d];
        float ml_ = g_mlt[(size_t)k * DK + d];
        float lg_ = g_lgt[(size_t)k * DK + d];
#pragma unroll
        for (int g = 0; g < 4; g++) {
            a[g]  = fmaf(wv_, ws[g][k],  a[g]);
            m2[g] = fmaf(ml_, mfs[g][k], m2[g]);
            lg[g] = fmaf(lg_, mns[g][k], lg[g]);
        }
    }
#pragma unroll
    for (int g = 0; g < 4; g++)
        feat[g][d] = fmaxf(a[g], 0.f) + fmaxf(m2[g], 0.f) + fmaxf(lg[g], 0.f);
    __syncthreads();
    float part[4] = {0.f, 0.f, 0.f, 0.f};
#pragma unroll
    for (int rep = 0; rep < 2; rep++) {
        int o = tid + rep * 256;
        float t[4];
        float pb = __ldg(ph1_b + o);
#pragma unroll
        for (int g = 0; g < 4; g++) t[g] = pb;
        for (int k = 0; k < DK; k++) {
            float w = g_ph1t[(size_t)k * 512 + o];
#pragma unroll
            for (int g = 0; g < 4; g++) t[g] = fmaf(w, feat[g][k], t[g]);
        }
        float p2 = __ldg(ph2_w + o);
#pragma unroll
        for (int g = 0; g < 4; g++) {
            float x = t[g];
            float sp = (x > 20.f) ? x : log1pf(expf(x));
            part[g] = fmaf(sp, p2, part[g]);
        }
    }
    for (int g = 0; g < 4; g++) {
        red[tid] = part[g];
        __syncthreads();
        for (int s = 128; s; s >>= 1) {
            if (tid < s) red[tid] += red[tid + s];
            __syncthreads();
        }
        if (tid == 0) out[b0 + g] = red[0] + __ldg(ph2_b);
        __syncthreads();
    }
}

// ---------------- launch ----------------
extern "C" void kernel_launch(void* const* d_in, const int* in_sizes, int n_in,
                              void* d_out, int out_size)
{
    const int*   x_type     = (const int*)d_in[0];
    const float* x_feat     = (const float*)d_in[1];
    const int*   edge_index = (const int*)d_in[2];
    const float* edge_attr  = (const float*)d_in[3];
    const int*   metal_type = (const int*)d_in[4];
    const float* metal_feat = (const float*)d_in[5];
    const float* x_emb      = (const float*)d_in[6];
    const float* x_weight   = (const float*)d_in[7];
    const float* ew1        = (const float*)d_in[8];
    const float* mlp_w      = (const float*)d_in[9];
    const float* mlp_b      = (const float*)d_in[10];
    const float* bn_g       = (const float*)d_in[11];
    const float* bn_b       = (const float*)d_in[12];
    const float* bn_rm      = (const float*)d_in[13];
    const float* bn_rv      = (const float*)d_in[14];
    const float* me1_w      = (const float*)d_in[15];
    const float* me1_b      = (const float*)d_in[16];
    const float* me2        = (const float*)d_in[17];
    const float* wq         = (const float*)d_in[18];
    const float* wk         = (const float*)d_in[19];
    const float* wv         = (const float*)d_in[20];
    const float* ml_w       = (const float*)d_in[21];
    const float* ml_b       = (const float*)d_in[22];
    const float* lg_w       = (const float*)d_in[23];
    const float* lg_b       = (const float*)d_in[24];
    const float* ph1_w      = (const float*)d_in[25];
    const float* ph1_b      = (const float*)d_in[26];
    const float* ph2_w      = (const float*)d_in[27];
    const float* ph2_b      = (const float*)d_in[28];
    float* out = (float*)d_out;

    cudaFuncSetAttribute(k_gemm_bulk, cudaFuncAttributeMaxDynamicSharedMemorySize, GEMM_SMEM);

    k_init_frag<<<NNODES / 16, 256>>>(x_type, x_feat, x_emb, x_weight);
    k_wsplit_frag<<<(NLAYERS * 2 * 20 * NKT * 32 + 255) / 256, 256>>>(mlp_w);
    k_mf<<<(BGR * EMB + 255) / 256, 256>>>(metal_type, metal_feat, me1_w, me1_b, me2);
    k_transpose_all<<<(4 * DK * EMB + 512 * DK + 255) / 256, 256>>>(wq, wv, ml_w, lg_w, ph1_w);
    k_ve_all<<<(NLAYERS * 2 * EMB * 32 + 255) / 256, 256>>>(ew1, mlp_w);

    // CSR build (once per launch)
    k_deg_init<<<(NNODES + 255) / 256, 256>>>();
    k_deg_count<<<(NEDGES + 255) / 256, 256>>>(edge_index);
    k_scan<<<1, 1024>>>();
    k_fill<<<(TOTE + 255) / 256, 256>>>(edge_index, edge_attr);

    dim3 gg(GRIDX, 2);
    for (int l = 0; l < NLAYERS; l++) {
        k_gemm_bulk<<<gg, 256, GEMM_SMEM>>>(l, mlp_b + (size_t)l * EMB);
        if (l < NLAYERS - 1)
            k_aggr_frag<<<NNODES / 16, 256>>>(
                l, bn_rm + (size_t)l * EMB, bn_rv + (size_t)l * EMB,
                bn_g + (size_t)l * EMB, bn_b + (size_t)l * EMB);
        else
            k_aggr_last<<<(NNODES * 32 + 255) / 256, 256>>>(
                l, bn_rm + (size_t)l * EMB, bn_rv + (size_t)l * EMB,
                bn_g + (size_t)l * EMB, bn_b + (size_t)l * EMB);
    }

    k_q<<<BGR / 4, 256>>>();
    k_qk<<<BGR / 4, 320>>>(wk);
    k_attn<<<BGR, 256>>>();
    k_final<<<BGR / 4, 256>>>(ml_b, lg_b, ph1_b, ph2_w, ph2_b, out);
}

// round 9
// speedup vs baseline: 1.8295x; 1.5209x over previous
#include <cuda_runtime.h>
#include <cuda_bf16.h>
#include <math.h>
#include <stdint.h>

#define NNODES 50000
#define NPADM  50176       // 196 * 256
#define NEDGES 200000
#define TOTE   (NEDGES + NNODES)
#define EMB    300
#define EMB4   75
#define KPAD   320
#define DK     256
#define BGR    1000
#define NPER   50
#define NLAYERS 5
#define PADF   16

// ---------------- scratch (device globals) ----------------
__device__ float g_h[NNODES * EMB];
__device__ float g_hW[NNODES * EMB];
__device__ __nv_bfloat16 g_hs_hi[NPADM * KPAD];
__device__ __nv_bfloat16 g_hs_lo[NPADM * KPAD];
__device__ __nv_bfloat16 g_ws_hi[NLAYERS * KPAD * KPAD];
__device__ __nv_bfloat16 g_ws_lo[NLAYERS * KPAD * KPAD];
__device__ float g_mf[BGR * EMB];
__device__ float g_ve_all[NLAYERS * 2 * EMB];
__device__ float g_Q[BGR * DK];
__device__ float g_qk[BGR * EMB];
__device__ float g_wsum[BGR * EMB];
__device__ float g_mean[BGR * EMB];
__device__ float g_wqt[EMB * DK];
__device__ float g_wvt[EMB * DK];
__device__ float g_mlt[EMB * DK];
__device__ float g_lgt[EMB * DK];
__device__ float g_ph1t[DK * 512];
// CSR
__device__ int g_deg[NNODES];
__device__ int g_off[NNODES + 1];
__device__ int g_cur[NNODES];
__device__ int g_csr_src[TOTE];
__device__ float2 g_csr_ea[TOTE];

// ---------------- helpers ----------------
__device__ __forceinline__ void store_split4(__nv_bfloat16* hh, __nv_bfloat16* hl, float4 v)
{
    float a[4] = {v.x, v.y, v.z, v.w};
    __nv_bfloat16 h[4], l[4];
#pragma unroll
    for (int q = 0; q < 4; q++) {
        h[q] = __float2bfloat16(a[q]);
        l[q] = __float2bfloat16(a[q] - __bfloat162float(h[q]));
    }
    *(__nv_bfloat162*)(hh)     = __halves2bfloat162(h[0], h[1]);
    *(__nv_bfloat162*)(hh + 2) = __halves2bfloat162(h[2], h[3]);
    *(__nv_bfloat162*)(hl)     = __halves2bfloat162(l[0], l[1]);
    *(__nv_bfloat162*)(hl + 2) = __halves2bfloat162(l[2], l[3]);
}

__device__ __forceinline__ uint32_t smem_u32(const void* p) {
    uint32_t a;
    asm("{ .reg .u64 t; cvta.to.shared.u64 t, %1; cvt.u32.u64 %0, t; }" : "=r"(a) : "l"(p));
    return a;
}

#define MMA_BF16(d, a, b) asm volatile( \
    "mma.sync.aligned.m16n8k16.row.col.f32.bf16.bf16.f32 " \
    "{%0,%1,%2,%3},{%4,%5,%6,%7},{%8,%9},{%0,%1,%2,%3};\n" \
    : "+f"(d[0]), "+f"(d[1]), "+f"(d[2]), "+f"(d[3]) \
    : "r"((a)[0]), "r"((a)[1]), "r"((a)[2]), "r"((a)[3]), "r"((b)[0]), "r"((b)[1]))

#define LDM4(r, a) asm volatile( \
    "ldmatrix.sync.aligned.m8n8.x4.shared.b16 {%0,%1,%2,%3}, [%4];" \
    : "=r"((r)[0]), "=r"((r)[1]), "=r"((r)[2]), "=r"((r)[3]) : "r"(a))
#define LDM2(r, a) asm volatile( \
    "ldmatrix.sync.aligned.m8n8.x2.shared.b16 {%0,%1}, [%2];" \
    : "=r"((r)[0]), "=r"((r)[1]) : "r"(a))
#define CPA16(dst, src) asm volatile( \
    "cp.async.cg.shared.global [%0], [%1], 16;" :: "r"(dst), "l"(src) : "memory")

// ---------------- node init (+ bf16 split write) ----------------
__global__ void k_init(const int* __restrict__ x_type, const float* __restrict__ x_feat,
                       const float* __restrict__ x_emb, const float* __restrict__ x_weight)
{
    int idx = blockIdx.x * blockDim.x + threadIdx.x;
    if (idx >= NNODES * EMB4) return;
    int n = idx / EMB4, c = idx % EMB4;
    int t = __ldg(x_type + n);
    float4 acc = __ldg((const float4*)(x_emb + (size_t)t * EMB) + c);
#pragma unroll
    for (int k = 0; k < PADF; k++) {
        float f = __ldg(x_feat + (size_t)n * PADF + k);
        float4 w = __ldg((const float4*)(x_weight + (size_t)k * EMB) + c);
        acc.x = fmaf(f, w.x, acc.x); acc.y = fmaf(f, w.y, acc.y);
        acc.z = fmaf(f, w.z, acc.z); acc.w = fmaf(f, w.w, acc.w);
    }
    ((float4*)g_h)[idx] = acc;
    store_split4(g_hs_hi + (size_t)n * KPAD + c * 4, g_hs_lo + (size_t)n * KPAD + c * 4, acc);
    if (c == 74) {
        __nv_bfloat162 z = __floats2bfloat162_rn(0.f, 0.f);
#pragma unroll
        for (int q = 0; q < 10; q++) {
            ((__nv_bfloat162*)(g_hs_hi + (size_t)n * KPAD + 300))[q] = z;
            ((__nv_bfloat162*)(g_hs_lo + (size_t)n * KPAD + 300))[q] = z;
        }
    }
}

// zero the padded rows 50000..50175 once (avoid NaN garbage in A tiles)
__global__ void k_zero_pad()
{
    int idx = blockIdx.x * blockDim.x + threadIdx.x;
    int total = (NPADM - NNODES) * (KPAD / 8);    // 176 rows * 40 ushort4-chunks
    if (idx >= total) return;
    int r = idx / (KPAD / 8), c = idx % (KPAD / 8);
    uint4 z = make_uint4(0, 0, 0, 0);
    ((uint4*)(g_hs_hi + (size_t)(NNODES + r) * KPAD))[c] = z;
    ((uint4*)(g_hs_lo + (size_t)(NNODES + r) * KPAD))[c] = z;
}

// ---------------- weight split (all layers, once) ----------------
__global__ void k_wsplit(const float* __restrict__ mlp_w)
{
    int idx = blockIdx.x * blockDim.x + threadIdx.x;
    if (idx >= NLAYERS * KPAD * KPAD) return;
    int l = idx / (KPAD * KPAD), rem = idx % (KPAD * KPAD);
    int j = rem / KPAD, k = rem % KPAD;
    float v = (j < EMB && k < EMB) ? __ldg(mlp_w + (size_t)l * EMB * EMB + (size_t)j * EMB + k) : 0.f;
    __nv_bfloat16 hi = __float2bfloat16(v);
    g_ws_hi[idx] = hi;
    g_ws_lo[idx] = __float2bfloat16(v - __bfloat162float(hi));
}

// ---------------- metal feature ----------------
__global__ void k_mf(const int* __restrict__ metal_type, const float* __restrict__ metal_feat,
                     const float* __restrict__ me1_w, const float* __restrict__ me1_b,
                     const float* __restrict__ me2)
{
    int idx = blockIdx.x * blockDim.x + threadIdx.x;
    if (idx >= BGR * EMB) return;
    int b = idx / EMB, j = idx % EMB;
    float acc = __ldg(me1_b + j) + __ldg(me2 + (size_t)__ldg(metal_type + b) * EMB + j);
#pragma unroll
    for (int k = 0; k < 17; k++)
        acc = fmaf(__ldg(metal_feat + (size_t)b * 17 + k), __ldg(me1_w + (size_t)j * 17 + k), acc);
    g_mf[idx] = acc;
}

// ---------------- transpose readout weights ----------------
__global__ void k_transpose_all(const float* __restrict__ wq, const float* __restrict__ wv,
                                const float* __restrict__ ml, const float* __restrict__ lg,
                                const float* __restrict__ ph1)
{
    int idx = blockIdx.x * blockDim.x + threadIdx.x;
    const int SZ1 = DK * EMB;
    if (idx < 4 * SZ1) {
        int w = idx / SZ1, i = idx % SZ1;
        int d = i / EMB, j = i % EMB;
        float v = (w == 0) ? wq[i] : (w == 1) ? wv[i] : (w == 2) ? ml[i] : lg[i];
        float* dst = (w == 0) ? g_wqt : (w == 1) ? g_wvt : (w == 2) ? g_mlt : g_lgt;
        dst[(size_t)j * DK + d] = v;
    } else {
        int i = idx - 4 * SZ1;
        if (i < 512 * DK) {
            int o = i / DK, d = i % DK;
            g_ph1t[(size_t)d * 512 + o] = ph1[i];
        }
    }
}

// ---------------- all layers' edge vectors ----------------
__global__ void k_ve_all(const float* __restrict__ ew1, const float* __restrict__ mlp_w)
{
    int o = (blockIdx.x * blockDim.x + threadIdx.x) >> 5;
    if (o >= NLAYERS * 2 * EMB) return;
    int lane = threadIdx.x & 31;
    int l = o / (2 * EMB);
    int rem = o % (2 * EMB);
    int w = rem / EMB, col = rem % EMB;
    const float* e = ew1 + (size_t)l * 2 * EMB + (size_t)w * EMB;
    const float* wr = mlp_w + (size_t)l * EMB * EMB + (size_t)col * EMB;
    float s = 0.f;
    for (int k = lane; k < EMB; k += 32) s = fmaf(__ldg(e + k), __ldg(wr + k), s);
#pragma unroll
    for (int off = 16; off; off >>= 1) s += __shfl_xor_sync(0xffffffffu, s, off);
    if (lane == 0) g_ve_all[o] = s;
}

// ---------------- CSR build ----------------
__global__ void k_deg_init() {
    int i = blockIdx.x * blockDim.x + threadIdx.x;
    if (i < NNODES) g_deg[i] = 1;
}
__global__ void k_deg_count(const int* __restrict__ eidx) {
    int e = blockIdx.x * blockDim.x + threadIdx.x;
    if (e < NEDGES) atomicAdd(&g_deg[__ldg(eidx + NEDGES + e)], 1);
}
__global__ void k_scan() {
    __shared__ int ps[1024];
    const int C = (NNODES + 1023) / 1024;
    int t = threadIdx.x;
    int base = t * C;
    int s = 0;
    for (int i = base; i < base + C && i < NNODES; i++) s += g_deg[i];
    ps[t] = s;
    __syncthreads();
    for (int off = 1; off < 1024; off <<= 1) {
        int v = (t >= off) ? ps[t - off] : 0;
        __syncthreads();
        ps[t] += v;
        __syncthreads();
    }
    int ex = (t == 0) ? 0 : ps[t - 1];
    for (int i = base; i < base + C && i < NNODES; i++) {
        g_off[i] = ex; g_cur[i] = ex;
        ex += g_deg[i];
    }
    if (t == 1023) g_off[NNODES] = TOTE;
}
__global__ void k_fill(const int* __restrict__ eidx, const float* __restrict__ eattr) {
    int idx = blockIdx.x * blockDim.x + threadIdx.x;
    if (idx >= TOTE) return;
    int src, col; float2 ea;
    if (idx < NEDGES) {
        src = __ldg(eidx + idx);
        col = __ldg(eidx + NEDGES + idx);
        ea = __ldg((const float2*)eattr + idx);
    } else {
        src = col = idx - NEDGES;
        ea = make_float2(0.f, 4.f);
    }
    int pos = atomicAdd(&g_cur[col], 1);
    g_csr_src[pos] = src;
    g_csr_ea[pos] = ea;
}

// ---------------- GEMM: hW = h @ W.T + b  (bf16 3-split, 256x160 tile, 512 thr) ---
// K chunks of 32, double-buffered cp.async. Row stride 80B (32 bf16 + 8 pad).
// Stage: A_hi@0 (256x80=20480), A_lo@20480, B_hi@40960 (160x80=12800), B_lo@53760;
// stage = 66560, double = 133120.
#define ROWB   80
#define OA_LO  20480
#define OB_HI  40960
#define OB_LO  53760
#define STG_SZ 66560
#define GEMM_SMEM (2 * STG_SZ)

__device__ __forceinline__ void gemm_prefetch(uint32_t sbase, int layer, int m0, int j0,
                                              int k0, int tid)
{
    // A: 2048 16B ops (hi 1024 + lo 1024)
#pragma unroll
    for (int it = 0; it < 4; it++) {
        int f = tid + it * 512;
        int sel = f >> 10, e = f & 1023;
        int r = e >> 2, c4 = e & 3;
        uint32_t dst = sbase + (sel ? OA_LO : 0) + r * ROWB + c4 * 16;
        const __nv_bfloat16* src = (sel ? g_hs_lo : g_hs_hi) + (size_t)(m0 + r) * KPAD + k0 + c4 * 8;
        CPA16(dst, src);
    }
    // B: 1280 16B ops (hi 640 + lo 640); j0 + r < 320 always (padded weights)
#pragma unroll
    for (int it = 0; it < 3; it++) {
        int f = tid + it * 512;
        if (f < 1280) {
            int sel = (f >= 640) ? 1 : 0;
            int e = sel ? f - 640 : f;
            int r = e >> 2, c4 = e & 3;
            uint32_t dst = sbase + (sel ? OB_LO : OB_HI) + r * ROWB + c4 * 16;
            const __nv_bfloat16* src = (sel ? g_ws_lo : g_ws_hi)
                                       + ((size_t)layer * KPAD + j0 + r) * KPAD + k0 + c4 * 8;
            CPA16(dst, src);
        }
    }
    asm volatile("cp.async.commit_group;" ::: "memory");
}

__global__ void __launch_bounds__(512) k_gemm_mma(int layer, const float* __restrict__ bias)
{
    extern __shared__ char smem[];
    uint32_t sb = smem_u32(smem);
    int tid = threadIdx.x, warp = tid >> 5, lane = tid & 31;
    int gid = lane >> 2, tig = lane & 3;
    int wm = warp & 3, wn = warp >> 2;       // 4 (M) x 4 (N) warps
    int m0 = blockIdx.x * 256, j0 = blockIdx.y * 160;

    float acc[4][5][4];
#pragma unroll
    for (int mt = 0; mt < 4; mt++)
#pragma unroll
        for (int nj = 0; nj < 5; nj++)
#pragma unroll
            for (int r = 0; r < 4; r++) acc[mt][nj][r] = 0.f;

    int arowB = (wm * 64 + (lane & 15)) * ROWB + 16 * (lane >> 4);
    int nb = wn * 40;
    int brow4B = (nb + 8 * (lane >> 4) + (lane & 7)) * ROWB + 16 * ((lane >> 3) & 1);
    int brow2B = (nb + 32 + (lane & 7)) * ROWB + 16 * ((lane >> 3) & 1);

    gemm_prefetch(sb, layer, m0, j0, 0, tid);

    for (int kc = 0; kc < 10; kc++) {
        int cur = kc & 1;
        asm volatile("cp.async.wait_group 0;" ::: "memory");
        __syncthreads();
        if (kc < 9)
            gemm_prefetch(sb + (1 - cur) * STG_SZ, layer, m0, j0, (kc + 1) * 32, tid);

        uint32_t Ab = sb + cur * STG_SZ;
#pragma unroll
        for (int ks = 0; ks < 2; ks++) {
            int kbB = ks * 32;
            uint32_t ah[4][4], al[4][4], bh[5][2], bl[5][2];
#pragma unroll
            for (int mt = 0; mt < 4; mt++)
                LDM4(ah[mt], Ab + arowB + mt * (16 * ROWB) + kbB);
#pragma unroll
            for (int pr = 0; pr < 2; pr++) {
                uint32_t t[4];
                LDM4(t, Ab + OB_HI + brow4B + pr * (16 * ROWB) + kbB);
                bh[2 * pr][0] = t[0]; bh[2 * pr][1] = t[1];
                bh[2 * pr + 1][0] = t[2]; bh[2 * pr + 1][1] = t[3];
            }
            LDM2(bh[4], Ab + OB_HI + brow2B + kbB);
            // pass 1: hi x hi
#pragma unroll
            for (int mt = 0; mt < 4; mt++)
#pragma unroll
                for (int nj = 0; nj < 5; nj++) MMA_BF16(acc[mt][nj], ah[mt], bh[nj]);
            // pass 2: lo x hi
#pragma unroll
            for (int mt = 0; mt < 4; mt++)
                LDM4(al[mt], Ab + OA_LO + arowB + mt * (16 * ROWB) + kbB);
#pragma unroll
            for (int mt = 0; mt < 4; mt++)
#pragma unroll
                for (int nj = 0; nj < 5; nj++) MMA_BF16(acc[mt][nj], al[mt], bh[nj]);
            // pass 3: hi x lo
#pragma unroll
            for (int pr = 0; pr < 2; pr++) {
                uint32_t t[4];
                LDM4(t, Ab + OB_LO + brow4B + pr * (16 * ROWB) + kbB);
                bl[2 * pr][0] = t[0]; bl[2 * pr][1] = t[1];
                bl[2 * pr + 1][0] = t[2]; bl[2 * pr + 1][1] = t[3];
            }
            LDM2(bl[4], Ab + OB_LO + brow2B + kbB);
#pragma unroll
            for (int mt = 0; mt < 4; mt++)
#pragma unroll
                for (int nj = 0; nj < 5; nj++) MMA_BF16(acc[mt][nj], ah[mt], bl[nj]);
        }
        __syncthreads();
    }

    // epilogue: + bias, store fp32
#pragma unroll
    for (int mt = 0; mt < 4; mt++) {
        int m = m0 + wm * 64 + mt * 16 + gid;
#pragma unroll
        for (int nj = 0; nj < 5; nj++) {
            int j = j0 + nb + nj * 8 + 2 * tig;
            if (j < EMB) {
                float b0 = __ldg(bias + j), b1 = __ldg(bias + j + 1);
                if (m < NNODES)
                    *(float2*)(g_hW + (size_t)m * EMB + j) =
                        make_float2(acc[mt][nj][0] + b0, acc[mt][nj][1] + b1);
                if (m + 8 < NNODES)
                    *(float2*)(g_hW + (size_t)(m + 8) * EMB + j) =
                        make_float2(acc[mt][nj][2] + b0, acc[mt][nj][3] + b1);
            }
        }
    }
}

// ---------------- pull aggregation + BN (+relu), fused; conditional stores -------
__global__ void __launch_bounds__(256) k_aggr(int layer,
                                              const float* __restrict__ rm,
                                              const float* __restrict__ rv,
                                              const float* __restrict__ gg,
                                              const float* __restrict__ bb,
                                              int do_relu, int store_h, int store_split)
{
    int gw = (blockIdx.x * blockDim.x + threadIdx.x) >> 5;
    if (gw >= NNODES) return;
    int lane = threadIdx.x & 31;
    const float4* ve4 = (const float4*)(g_ve_all + (size_t)layer * 2 * EMB);

    float4 acc[3], e0[3], e1[3];
#pragma unroll
    for (int i = 0; i < 3; i++) {
        acc[i] = make_float4(0.f, 0.f, 0.f, 0.f);
        int c = lane + 32 * i;
        if (c < EMB4) { e0[i] = __ldg(ve4 + c); e1[i] = __ldg(ve4 + EMB4 + c); }
    }
    int beg = g_off[gw], end = g_off[gw + 1];
    for (int e = beg; e < end; e++) {
        int src = g_csr_src[e];
        float2 ea = g_csr_ea[e];
        const float4* row = (const float4*)(g_hW + (size_t)src * EMB);
#pragma unroll
        for (int i = 0; i < 3; i++) {
            int c = lane + 32 * i;
            if (c < EMB4) {
                float4 x = row[c];
                acc[i].x += fmaxf(fmaf(ea.y, e1[i].x, fmaf(ea.x, e0[i].x, x.x)), 0.f);
                acc[i].y += fmaxf(fmaf(ea.y, e1[i].y, fmaf(ea.x, e0[i].y, x.y)), 0.f);
                acc[i].z += fmaxf(fmaf(ea.y, e1[i].z, fmaf(ea.x, e0[i].z, x.z)), 0.f);
                acc[i].w += fmaxf(fmaf(ea.y, e1[i].w, fmaf(ea.x, e0[i].w, x.w)), 0.f);
            }
        }
    }
#pragma unroll
    for (int i = 0; i < 3; i++) {
        int c = lane + 32 * i;
        if (c < EMB4) {
            float4 m = __ldg((const float4*)rm + c);
            float4 v = __ldg((const float4*)rv + c);
            float4 g4 = __ldg((const float4*)gg + c);
            float4 b4 = __ldg((const float4*)bb + c);
            float4 y;
            y.x = (acc[i].x - m.x) * rsqrtf(v.x + 1e-5f) * g4.x + b4.x;
            y.y = (acc[i].y - m.y) * rsqrtf(v.y + 1e-5f) * g4.y + b4.y;
            y.z = (acc[i].z - m.z) * rsqrtf(v.z + 1e-5f) * g4.z + b4.z;
            y.w = (acc[i].w - m.w) * rsqrtf(v.w + 1e-5f) * g4.w + b4.w;
            if (do_relu) {
                y.x = fmaxf(y.x, 0.f); y.y = fmaxf(y.y, 0.f);
                y.z = fmaxf(y.z, 0.f); y.w = fmaxf(y.w, 0.f);
            }
            if (store_h) ((float4*)(g_h + (size_t)gw * EMB))[c] = y;
            if (store_split)
                store_split4(g_hs_hi + (size_t)gw * KPAD + c * 4,
                             g_hs_lo + (size_t)gw * KPAD + c * 4, y);
        }
    }
}

// ---------------- readout ----------------
__global__ void k_q()
{
    __shared__ float mfs[4][EMB];
    int b0 = blockIdx.x * 4, tid = threadIdx.x;
    for (int i = tid; i < 4 * EMB; i += 256)
        mfs[i / EMB][i % EMB] = g_mf[(size_t)(b0 + i / EMB) * EMB + i % EMB];
    __syncthreads();
    float acc[4] = {0.f, 0.f, 0.f, 0.f};
    for (int j = 0; j < EMB; j++) {
        float w = g_wqt[(size_t)j * DK + tid];
#pragma unroll
        for (int g = 0; g < 4; g++) acc[g] = fmaf(mfs[g][j], w, acc[g]);
    }
#pragma unroll
    for (int g = 0; g < 4; g++) g_Q[(size_t)(b0 + g) * DK + tid] = acc[g];
}

__global__ void k_qk(const float* __restrict__ wk)
{
    __shared__ float Qs[4][DK];
    int b0 = blockIdx.x * 4, tid = threadIdx.x;
    for (int i = tid; i < 4 * DK; i += 320)
        Qs[i / DK][i % DK] = g_Q[(size_t)(b0 + i / DK) * DK + i % DK];
    __syncthreads();
    if (tid < EMB) {
        float acc[4] = {0.f, 0.f, 0.f, 0.f};
        for (int d = 0; d < DK; d++) {
            float w = __ldg(wk + (size_t)d * EMB + tid);
#pragma unroll
            for (int g = 0; g < 4; g++) acc[g] = fmaf(Qs[g][d], w, acc[g]);
        }
#pragma unroll
        for (int g = 0; g < 4; g++) g_qk[(size_t)(b0 + g) * EMB + tid] = acc[g];
    }
}

__global__ void k_attn()
{
    __shared__ float qks[EMB];
    __shared__ float sc[NPER];
    __shared__ float p[NPER];
    int b = blockIdx.x, tid = threadIdx.x;
    for (int i = tid; i < EMB; i += 256) qks[i] = g_qk[(size_t)b * EMB + i];
    __syncthreads();
    int warp = tid >> 5, lane = tid & 31;
    const float* hb = g_h + (size_t)b * NPER * EMB;
    for (int k = warp; k < NPER; k += 8) {
        float s = 0.f;
        for (int i = lane; i < EMB; i += 32) s = fmaf(qks[i], hb[(size_t)k * EMB + i], s);
#pragma unroll
        for (int off = 16; off; off >>= 1) s += __shfl_xor_sync(0xffffffffu, s, off);
        if (lane == 0) sc[k] = s * (1.0f / 16.0f);
    }
    __syncthreads();
    if (tid == 0) {
        float mx = -1e30f;
        for (int k = 0; k < NPER; k++) mx = fmaxf(mx, sc[k]);
        float ssum = 0.f;
        for (int k = 0; k < NPER; k++) { float e = expf(sc[k] - mx); p[k] = e; ssum += e; }
        float inv = 1.f / ssum;
        for (int k = 0; k < NPER; k++) p[k] *= inv;
    }
    __syncthreads();
    for (int j = tid; j < EMB; j += 256) {
        float ws = 0.f, mn = 0.f;
        for (int k = 0; k < NPER; k++) {
            float v = hb[(size_t)k * EMB + j];
            ws = fmaf(p[k], v, ws); mn += v;
        }
        g_wsum[(size_t)b * EMB + j] = ws;
        g_mean[(size_t)b * EMB + j] = mn * (1.0f / NPER);
    }
}

__global__ void k_final(const float* __restrict__ ml_b, const float* __restrict__ lg_b,
                        const float* __restrict__ ph1_b, const float* __restrict__ ph2_w,
                        const float* __restrict__ ph2_b, float* __restrict__ out)
{
    __shared__ float ws[4][EMB], mfs[4][EMB], mns[4][EMB];
    __shared__ float feat[4][DK];
    __shared__ float red[256];
    int b0 = blockIdx.x * 4, tid = threadIdx.x;
    for (int i = tid; i < 4 * EMB; i += 256) {
        int g = i / EMB, j = i % EMB;
        ws[g][j]  = g_wsum[(size_t)(b0 + g) * EMB + j];
        mfs[g][j] = g_mf[(size_t)(b0 + g) * EMB + j];
        mns[g][j] = g_mean[(size_t)(b0 + g) * EMB + j];
    }
    __syncthreads();
    int d = tid;
    float a[4], m2[4], lg[4];
    float mb = __ldg(ml_b + d), lb = __ldg(lg_b + d);
#pragma unroll
    for (int g = 0; g < 4; g++) { a[g] = 0.f; m2[g] = mb; lg[g] = lb; }
    for (int k = 0; k < EMB; k++) {
        float wv_ = g_wvt[(size_t)k * DK + d];
        float ml_ = g_mlt[(size_t)k * DK + d];
        float lg_ = g_lgt[(size_t)k * DK + d];
#pragma unroll
        for (int g = 0; g < 4; g++) {
            a[g]  = fmaf(wv_, ws[g][k],  a[g]);
            m2[g] = fmaf(ml_, mfs[g][k], m2[g]);
            lg[g] = fmaf(lg_, mns[g][k], lg[g]);
        }
    }
#pragma unroll
    for (int g = 0; g < 4; g++)
        feat[g][d] = fmaxf(a[g], 0.f) + fmaxf(m2[g], 0.f) + fmaxf(lg[g], 0.f);
    __syncthreads();
    float part[4] = {0.f, 0.f, 0.f, 0.f};
#pragma unroll
    for (int rep = 0; rep < 2; rep++) {
        int o = tid + rep * 256;
        float t[4];
        float pb = __ldg(ph1_b + o);
#pragma unroll
        for (int g = 0; g < 4; g++) t[g] = pb;
        for (int k = 0; k < DK; k++) {
            float w = g_ph1t[(size_t)k * 512 + o];
#pragma unroll
            for (int g = 0; g < 4; g++) t[g] = fmaf(w, feat[g][k], t[g]);
        }
        float p2 = __ldg(ph2_w + o);
#pragma unroll
        for (int g = 0; g < 4; g++) {
            float x = t[g];
            float sp = (x > 20.f) ? x : log1pf(expf(x));
            part[g] = fmaf(sp, p2, part[g]);
        }
    }
    for (int g = 0; g < 4; g++) {
        red[tid] = part[g];
        __syncthreads();
        for (int s = 128; s; s >>= 1) {
            if (tid < s) red[tid] += red[tid + s];
            __syncthreads();
        }
        if (tid == 0) out[b0 + g] = red[0] + __ldg(ph2_b);
        __syncthreads();
    }
}

// ---------------- launch ----------------
extern "C" void kernel_launch(void* const* d_in, const int* in_sizes, int n_in,
                              void* d_out, int out_size)
{
    const int*   x_type     = (const int*)d_in[0];
    const float* x_feat     = (const float*)d_in[1];
    const int*   edge_index = (const int*)d_in[2];
    const float* edge_attr  = (const float*)d_in[3];
    const int*   metal_type = (const int*)d_in[4];
    const float* metal_feat = (const float*)d_in[5];
    const float* x_emb      = (const float*)d_in[6];
    const float* x_weight   = (const float*)d_in[7];
    const float* ew1        = (const float*)d_in[8];
    const float* mlp_w      = (const float*)d_in[9];
    const float* mlp_b      = (const float*)d_in[10];
    const float* bn_g       = (const float*)d_in[11];
    const float* bn_b       = (const float*)d_in[12];
    const float* bn_rm      = (const float*)d_in[13];
    const float* bn_rv      = (const float*)d_in[14];
    const float* me1_w      = (const float*)d_in[15];
    const float* me1_b      = (const float*)d_in[16];
    const float* me2        = (const float*)d_in[17];
    const float* wq         = (const float*)d_in[18];
    const float* wk         = (const float*)d_in[19];
    const float* wv         = (const float*)d_in[20];
    const float* ml_w       = (const float*)d_in[21];
    const float* ml_b       = (const float*)d_in[22];
    const float* lg_w       = (const float*)d_in[23];
    const float* lg_b       = (const float*)d_in[24];
    const float* ph1_w      = (const float*)d_in[25];
    const float* ph1_b      = (const float*)d_in[26];
    const float* ph2_w      = (const float*)d_in[27];
    const float* ph2_b      = (const float*)d_in[28];
    float* out = (float*)d_out;

    cudaFuncSetAttribute(k_gemm_mma, cudaFuncAttributeMaxDynamicSharedMemorySize, GEMM_SMEM);

    k_init<<<(NNODES * EMB4 + 255) / 256, 256>>>(x_type, x_feat, x_emb, x_weight);
    k_zero_pad<<<((NPADM - NNODES) * (KPAD / 8) + 255) / 256, 256>>>();
    k_wsplit<<<(NLAYERS * KPAD * KPAD + 255) / 256, 256>>>(mlp_w);
    k_mf<<<(BGR * EMB + 255) / 256, 256>>>(metal_type, metal_feat, me1_w, me1_b, me2);
    k_transpose_all<<<(4 * DK * EMB + 512 * DK + 255) / 256, 256>>>(wq, wv, ml_w, lg_w, ph1_w);
    k_ve_all<<<(NLAYERS * 2 * EMB * 32 + 255) / 256, 256>>>(ew1, mlp_w);

    // CSR build (once per launch)
    k_deg_init<<<(NNODES + 255) / 256, 256>>>();
    k_deg_count<<<(NEDGES + 255) / 256, 256>>>(edge_index);
    k_scan<<<1, 1024>>>();
    k_fill<<<(TOTE + 255) / 256, 256>>>(edge_index, edge_attr);

    dim3 gg(NPADM / 256, 2);
    for (int l = 0; l < NLAYERS; l++) {
        int last = (l == NLAYERS - 1);
        k_gemm_mma<<<gg, 512, GEMM_SMEM>>>(l, mlp_b + (size_t)l * EMB);
        k_aggr<<<(NNODES * 32 + 255) / 256, 256>>>(
            l,
            bn_rm + (size_t)l * EMB, bn_rv + (size_t)l * EMB,
            bn_g + (size_t)l * EMB, bn_b + (size_t)l * EMB,
            last ? 0 : 1, last ? 1 : 0, last ? 0 : 1);
    }

    k_q<<<BGR / 4, 256>>>();
    k_qk<<<BGR / 4, 320>>>(wk);
    k_attn<<<BGR, 256>>>();
    k_final<<<BGR / 4, 256>>>(ml_b, lg_b, ph1_b, ph2_w, ph2_b, out);
}